// round 16
// baseline (speedup 1.0000x reference)
#include <cuda_runtime.h>
#include <cuda_fp16.h>
#include <math.h>
#include <stdint.h>

#define NSEG 256      // B*M
#define MLAB 32       // M
#define BSUB 8        // B
#define DELTA_V 0.5f
#define TWO_DELTA_D 3.0f

#define GRID 296      // 2 CTAs/SM * 148 SMs
#define TPB  512
#define TILE 512      // points per tile
#define MAXN 2097152  // problem N

#define DATA_B  (TILE * 64)               // 32768 bytes of point data
#define LAB_OFF DATA_B
#define SBI_OFF (DATA_B + TILE * 4)
#define STAGE_B (DATA_B + 2 * TILE * 4)   // 36864
#define DYN_B   (2 * STAGE_B)             // 73728

// ---------------- device scratch (self-cleaning across graph replays) ----
__device__ float    g_sums[NSEG * 16] = {};
__device__ float    g_cnts[NSEG]      = {};
__device__ float    g_pull = 0.0f;
__device__ float    g_push = 0.0f;
__device__ unsigned g_bar1 = 0u;
__device__ unsigned g_bar2 = 0u;
// compressed mirror written by phase A, read by phase C (L2-resident)
__device__ __half          h_data[(size_t)MAXN * 16];   // 64 MB
__device__ unsigned short  h_seg[MAXN];                 // 4 MB

#define SH_FLOATS (NSEG * 17 + NSEG + 32)

// pack two floats -> one u32 of fp16x2
__device__ __forceinline__ unsigned pack_h2(float a, float b) {
    __half2 h = __floats2half2_rn(a, b);
    return *reinterpret_cast<unsigned*>(&h);
}
// unpack u32 of fp16x2 -> float2
__device__ __forceinline__ float2 unpack_h2(unsigned u) {
    __half2 h = *reinterpret_cast<__half2*>(&u);
    return __half22float2(h);
}

// ---------------- mbarrier / bulk-copy helpers ----------------
__device__ __forceinline__ void mbar_init(unsigned a, unsigned cnt) {
    asm volatile("mbarrier.init.shared.b64 [%0], %1;" :: "r"(a), "r"(cnt) : "memory");
}
__device__ __forceinline__ void mbar_expect(unsigned a, unsigned tx) {
    asm volatile("mbarrier.arrive.expect_tx.shared.b64 _, [%0], %1;"
                 :: "r"(a), "r"(tx) : "memory");
}
__device__ __forceinline__ void mbar_wait(unsigned a, unsigned parity) {
    unsigned done = 0;
    while (!done) {
        asm volatile(
            "{\n\t.reg .pred p;\n\t"
            "mbarrier.try_wait.parity.acquire.cta.shared::cta.b64 p, [%1], %2, 0x989680;\n\t"
            "selp.b32 %0, 1, 0, p;\n\t}"
            : "=r"(done) : "r"(a), "r"(parity) : "memory");
    }
}
__device__ __forceinline__ void bulk_g2s(void* dst, const void* src,
                                         unsigned bytes, unsigned mbar,
                                         unsigned long long pol) {
    unsigned d = (unsigned)__cvta_generic_to_shared(dst);
    asm volatile(
        "cp.async.bulk.shared::cta.global.mbarrier::complete_tx::bytes.L2::cache_hint "
        "[%0], [%1], %2, [%3], %4;"
        :: "r"(d), "l"(src), "r"(bytes), "r"(mbar), "l"(pol) : "memory");
}

__device__ __forceinline__ void issue_tile(char* stg, unsigned mbar,
                                           const char* gdata,
                                           const int* lab, const int* sbi,
                                           int tile_base, unsigned long long pol) {
    mbar_expect(mbar, STAGE_B);
    bulk_g2s(stg,           gdata + (size_t)tile_base * 64, DATA_B,   mbar, pol);
    bulk_g2s(stg + LAB_OFF, lab + tile_base,                TILE * 4, mbar, pol);
    bulk_g2s(stg + SBI_OFF, sbi + tile_base,                TILE * 4, mbar, pol);
}

__device__ __forceinline__ float dot16(const float4& a, const float4& b,
                                       const float4& c, const float4& e) {
    return a.x*a.x + a.y*a.y + a.z*a.z + a.w*a.w
         + b.x*b.x + b.y*b.y + b.z*b.z + b.w*b.w
         + c.x*c.x + c.y*c.y + c.z*c.z + c.w*c.w
         + e.x*e.x + e.y*e.y + e.z*e.z + e.w*e.w;
}

__global__ __launch_bounds__(TPB, 2)
void k_fused(const float4* __restrict__ out4,
             const int* __restrict__ lab,
             const int* __restrict__ sbi,
             int n, float* __restrict__ out) {
    extern __shared__ char dynsm[];
    __shared__ float sh[SH_FLOATS];
    __shared__ unsigned long long mbars[2];
    __shared__ int sh_last;
    float* s_sum = sh;                 // stride 17 (phase A)
    float* s_mu  = sh;                 // dense stride 16 (phase C)
    float* s_cnt = sh + NSEG * 17;     // also s_iv in phase C
    float* s_red = sh + NSEG * 17 + NSEG;

    const int t   = threadIdx.x;
    const int bd  = TPB;
    const int wid = t >> 5, lid = t & 31;
    const int pg  = t >> 2;            // point-group (4 lanes per point)
    const int c4  = t & 3;             // chunk within point
    const char* gdata = (const char*)out4;

    unsigned long long pol_first;      // stream: evict_first (protect mirror in L2)
    asm("createpolicy.fractional.L2::evict_first.b64 %0, 1.0;" : "=l"(pol_first));

    unsigned mb[2];
    {
        unsigned base = (unsigned)__cvta_generic_to_shared(mbars);
        mb[0] = base; mb[1] = base + 8;
    }
    if (t == 0) { mbar_init(mb[0], 1); mbar_init(mb[1], 1); }
    asm volatile("fence.proxy.async.shared::cta;" ::: "memory");
    __syncthreads();

    // ---- chunk for this block ----
    int per = (n + GRID - 1) / GRID;
    per = ((per + bd - 1) / bd) * bd;
    int start = blockIdx.x * per;
    int end   = start + per; if (end > n) end = n;
    const int cnt_pts = (end > start) ? (end - start) : 0;
    const int nt  = cnt_pts / TILE;
    const int rem = cnt_pts - nt * TILE;

    // ================= PHASE A : segment sums + write fp16 mirror =========
    for (int i = t; i < NSEG * 17; i += bd) s_sum[i] = 0.0f;
    for (int i = t; i < NSEG; i += bd)      s_cnt[i] = 0.0f;
    __syncthreads();

    {
        float4 acc = make_float4(0.f, 0.f, 0.f, 0.f);
        float  cw  = 0.0f;
        int    cur = -1;

        auto flush = [&]() {
            if (cur >= 0) {
                atomicAdd(&s_sum[cur * 17 + c4 * 4 + 0], acc.x);
                atomicAdd(&s_sum[cur * 17 + c4 * 4 + 1], acc.y);
                atomicAdd(&s_sum[cur * 17 + c4 * 4 + 2], acc.z);
                atomicAdd(&s_sum[cur * 17 + c4 * 4 + 3], acc.w);
                if (c4 == 0) atomicAdd(&s_cnt[cur], cw);
            }
        };

        if (t == 0) {
            if (nt > 0) issue_tile(dynsm,           mb[0], gdata, lab, sbi, start,        pol_first);
            if (nt > 1) issue_tile(dynsm + STAGE_B, mb[1], gdata, lab, sbi, start + TILE, pol_first);
        }

        for (int k = 0; k < nt; k++) {
            mbar_wait(mb[k & 1], (k >> 1) & 1);
            char* stg = dynsm + (k & 1) * STAGE_B;
            const int tile_base = start + k * TILE;
#pragma unroll
            for (int j = 0; j < TILE / 128; j++) {
                int q = pg + j * 128;                   // label-invariant stride
                float4 v = *(const float4*)(stg + q * 64 + c4 * 16);
                int l = ((const int*)(stg + LAB_OFF))[q];
                int s = ((const int*)(stg + SBI_OFF))[q];
                float pd = v.x*v.x + v.y*v.y + v.z*v.z + v.w*v.w;
                pd += __shfl_xor_sync(0xFFFFFFFFu, pd, 1);
                pd += __shfl_xor_sync(0xFFFFFFFFu, pd, 2);
                float inv = rsqrtf(pd);
                int seg = s * MLAB + l;
                float nx = v.x * inv, ny = v.y * inv,
                      nz = v.z * inv, nw = v.w * inv;
                // write fp16 mirror (stays dirty in L2; stream is evict_first)
                int gp = tile_base + q;
                {
                    uint2 packed = make_uint2(pack_h2(nx, ny), pack_h2(nz, nw));
                    *(uint2*)((char*)h_data + (size_t)gp * 32 + c4 * 8) = packed;
                    if (c4 == 0) h_seg[gp] = (unsigned short)seg;
                }
                if (seg != cur) {
                    flush();
                    cur = seg; cw = 0.0f;
                    acc = make_float4(0.f, 0.f, 0.f, 0.f);
                }
                acc.x += nx;  acc.y += ny;
                acc.z += nz;  acc.w += nw;
                cw += 1.0f;
            }
            __syncthreads();
            if (t == 0 && k + 2 < nt)
                issue_tile(stg, mb[k & 1], gdata, lab, sbi,
                           start + (k + 2) * TILE, pol_first);
        }
        // ragged tail: direct scalar path (also writes mirror)
        if (t < rem) {
            int p = start + nt * TILE + t;
            const float4* r = out4 + (size_t)p * 4;
            float4 a = r[0], b = r[1], c = r[2], e = r[3];
            float inv = rsqrtf(dot16(a, b, c, e));
            int seg = sbi[p] * MLAB + lab[p];
            float xs[16] = {a.x,a.y,a.z,a.w, b.x,b.y,b.z,b.w,
                            c.x,c.y,c.z,c.w, e.x,e.y,e.z,e.w};
            uint2* hd = (uint2*)((char*)h_data + (size_t)p * 32);
#pragma unroll
            for (int d = 0; d < 16; d++) atomicAdd(&s_sum[seg * 17 + d], xs[d] * inv);
#pragma unroll
            for (int d = 0; d < 4; d++)
                hd[d] = make_uint2(pack_h2(xs[d*4+0] * inv, xs[d*4+1] * inv),
                                   pack_h2(xs[d*4+2] * inv, xs[d*4+3] * inv));
            h_seg[p] = (unsigned short)seg;
            atomicAdd(&s_cnt[seg], 1.0f);
        }
        flush();
    }
    __syncthreads();

    // block flush -> global atomics
    for (int s = t; s < NSEG; s += bd) {
        float c0 = s_cnt[s];
        if (c0 != 0.0f) {
            atomicAdd(&g_cnts[s], c0);
#pragma unroll
            for (int d = 0; d < 16; d++)
                atomicAdd(&g_sums[s * 16 + d], s_sum[s * 17 + d]);
        }
    }

    // ================= GRID BARRIER =================
    __threadfence();
    __syncthreads();
    if (t == 0) {
        atomicAdd(&g_bar1, 1u);
        while (atomicAdd(&g_bar1, 0u) < (unsigned)GRID) { __nanosleep(64); }
    }
    __syncthreads();
    __threadfence();

    // ================= PHASE B : centroids (replicated per block) =========
    if (t < NSEG) {
        float c  = __ldcg(&g_cnts[t]);
        float ic = 1.0f / c;
        const float4* gs = (const float4*)&g_sums[t * 16];
        float4 m0 = __ldcg(gs + 0), m1 = __ldcg(gs + 1),
               m2 = __ldcg(gs + 2), m3 = __ldcg(gs + 3);
        float4* sm = (float4*)&s_mu[t * 16];
        m0.x *= ic; m0.y *= ic; m0.z *= ic; m0.w *= ic;
        m1.x *= ic; m1.y *= ic; m1.z *= ic; m1.w *= ic;
        m2.x *= ic; m2.y *= ic; m2.z *= ic; m2.w *= ic;
        m3.x *= ic; m3.y *= ic; m3.z *= ic; m3.w *= ic;
        sm[0] = m0; sm[1] = m1; sm[2] = m2; sm[3] = m3;
        s_cnt[t] = 1.0f / ((float)MLAB * c);    // s_iv
    }
    __syncthreads();

    // push term: block 0 only
    if (blockIdx.x == 0) {
        float h = 0.0f;
        if (t < NSEG) {
            int b = t >> 5, ii = t & 31;
            const float* mi = &s_mu[t * 16];
            for (int j = 0; j < MLAB; j++) {
                if (j == ii) continue;
                const float* mj = &s_mu[(b * 32 + j) * 16];
                float pd = 0.0f;
#pragma unroll
                for (int d = 0; d < 16; d++) pd += fabsf(mi[d] - mj[d]);
                float tt = TWO_DELTA_D - pd;
                if (tt > 0.0f) h += tt * tt;
            }
        }
        for (int off = 16; off > 0; off >>= 1)
            h += __shfl_down_sync(0xFFFFFFFFu, h, off);
        if (lid == 0) s_red[wid] = h;
        __syncthreads();
        if (t == 0) {
            float v = 0.0f;
            for (int w = 0; w < TPB / 32; w++) v += s_red[w];
            g_push = v / ((float)MLAB * (float)(MLAB - 1));
        }
        __syncthreads();
    }

    // ================= PHASE C : pull term from fp16 mirror (L2-hot) ======
    float local = 0.0f;
    {
        auto cpt = [&](int q) {
            uint2 hraw = *(const uint2*)((const char*)h_data + (size_t)q * 32 + c4 * 8);
            int seg = (int)h_seg[q];
            float2 f01 = unpack_h2(hraw.x);
            float2 f23 = unpack_h2(hraw.y);
            float4 m = *(const float4*)&s_mu[seg * 16 + c4 * 4];
            float pdist = fabsf(f01.x - m.x) + fabsf(f01.y - m.y)
                        + fabsf(f23.x - m.z) + fabsf(f23.y - m.w);
            pdist += __shfl_xor_sync(0xFFFFFFFFu, pdist, 1);
            pdist += __shfl_xor_sync(0xFFFFFFFFu, pdist, 2);
            if (c4 == 0) {
                float tt = pdist - DELTA_V;
                if (tt > 0.0f) local += tt * tt * s_cnt[seg];   // s_iv
            }
        };
        const int full = cnt_pts / 128;            // 128 points per iteration
        const int tail = cnt_pts - full * 128;
        int it = 0;
        for (; it + 2 <= full; it += 2) {          // 2-pt batch for MLP
            cpt(start + it * 128 + pg);
            cpt(start + (it + 1) * 128 + pg);
        }
        for (; it < full; it++) cpt(start + it * 128 + pg);
        if (pg < tail) cpt(start + full * 128 + pg);
    }

    // block reduction of pull
    for (int off = 16; off > 0; off >>= 1)
        local += __shfl_down_sync(0xFFFFFFFFu, local, off);
    if (lid == 0) s_red[wid] = local;
    __syncthreads();
    if (t == 0) {
        float v = 0.0f;
        for (int w = 0; w < TPB / 32; w++) v += s_red[w];
        atomicAdd(&g_pull, v);
    }

    // ================= EXIT: last block finalizes + resets ================
    if (t == 0) {
        __threadfence();
        unsigned old = atomicAdd(&g_bar2, 1u);
        sh_last = (old == (unsigned)GRID - 1u) ? 1 : 0;
    }
    __syncthreads();
    if (sh_last) {
        for (int i = t; i < NSEG * 16; i += bd) g_sums[i] = 0.0f;
        for (int i = t; i < NSEG; i += bd)      g_cnts[i] = 0.0f;
        if (t == 0) {
            float pull = atomicAdd(&g_pull, 0.0f);
            float push = g_push;
            out[0] = (pull + push) * (1.0f / (float)BSUB);
            g_pull = 0.0f;
            g_push = 0.0f;
            g_bar1 = 0u;
            g_bar2 = 0u;
        }
    }
}

extern "C" void kernel_launch(void* const* d_in, const int* in_sizes, int n_in,
                              void* d_out, int out_size) {
    const float4* out4 = (const float4*)d_in[0];
    const int*    lab  = (const int*)d_in[1];
    const int*    sbi  = (const int*)d_in[2];
    float* out = (float*)d_out;
    int n = in_sizes[1];   // N points

    static bool attr_ok = false;
    if (!attr_ok) {
        cudaError_t e = cudaFuncSetAttribute(
            k_fused, cudaFuncAttributeMaxDynamicSharedMemorySize, DYN_B);
        attr_ok = (e == cudaSuccess);
    }
    k_fused<<<GRID, TPB, DYN_B>>>(out4, lab, sbi, n, out);
}

// round 17
// speedup vs baseline: 1.1405x; 1.1405x over previous
#include <cuda_runtime.h>
#include <math.h>
#include <stdint.h>

#define NSEG 256      // B*M
#define MLAB 32       // M
#define BSUB 8        // B
#define DELTA_V 0.5f
#define TWO_DELTA_D 3.0f

#define GRID 296      // 2 CTAs/SM * 148 SMs
#define TPB  512
#define TILE 512      // points per tile

#define DATA_B  (TILE * 64)               // 32768 bytes of point data
#define LAB_OFF DATA_B
#define SBI_OFF (DATA_B + TILE * 4)
#define STAGE_B (DATA_B + 2 * TILE * 4)   // 36864
#define DYN_B   (2 * STAGE_B)             // 73728

// ---------------- device scratch (self-cleaning across graph replays) ----
__device__ float    g_sums[NSEG * 16] = {};
__device__ float    g_cnts[NSEG]      = {};
__device__ float    g_pull = 0.0f;
__device__ float    g_push = 0.0f;
__device__ unsigned g_bar1 = 0u;
__device__ unsigned g_bar2 = 0u;

#define SH_FLOATS (NSEG * 17 + NSEG + 32)

// ---------------- mbarrier / bulk-copy helpers ----------------
__device__ __forceinline__ void mbar_init(unsigned a, unsigned cnt) {
    asm volatile("mbarrier.init.shared.b64 [%0], %1;" :: "r"(a), "r"(cnt) : "memory");
}
__device__ __forceinline__ void mbar_expect(unsigned a, unsigned tx) {
    asm volatile("mbarrier.arrive.expect_tx.shared.b64 _, [%0], %1;"
                 :: "r"(a), "r"(tx) : "memory");
}
__device__ __forceinline__ void mbar_wait(unsigned a, unsigned parity) {
    unsigned done = 0;
    while (!done) {
        asm volatile(
            "{\n\t.reg .pred p;\n\t"
            "mbarrier.try_wait.parity.acquire.cta.shared::cta.b64 p, [%1], %2, 0x989680;\n\t"
            "selp.b32 %0, 1, 0, p;\n\t}"
            : "=r"(done) : "r"(a), "r"(parity) : "memory");
    }
}
__device__ __forceinline__ void bulk_g2s(void* dst, const void* src,
                                         unsigned bytes, unsigned mbar) {
    unsigned d = (unsigned)__cvta_generic_to_shared(dst);
    asm volatile(
        "cp.async.bulk.shared::cta.global.mbarrier::complete_tx::bytes [%0], [%1], %2, [%3];"
        :: "r"(d), "l"(src), "r"(bytes), "r"(mbar) : "memory");
}

__device__ __forceinline__ void issue_tile(char* stg, unsigned mbar,
                                           const char* gdata,
                                           const int* lab, const int* sbi,
                                           int tile_base) {
    mbar_expect(mbar, STAGE_B);
    bulk_g2s(stg,           gdata + (size_t)tile_base * 64, DATA_B,   mbar);
    bulk_g2s(stg + LAB_OFF, lab + tile_base,                TILE * 4, mbar);
    bulk_g2s(stg + SBI_OFF, sbi + tile_base,                TILE * 4, mbar);
}

__device__ __forceinline__ float dot16(const float4& a, const float4& b,
                                       const float4& c, const float4& e) {
    return a.x*a.x + a.y*a.y + a.z*a.z + a.w*a.w
         + b.x*b.x + b.y*b.y + b.z*b.z + b.w*b.w
         + c.x*c.x + c.y*c.y + c.z*c.z + c.w*c.w
         + e.x*e.x + e.y*e.y + e.z*e.z + e.w*e.w;
}

__global__ __launch_bounds__(TPB, 2)
void k_fused(const float4* __restrict__ out4,
             const int* __restrict__ lab,
             const int* __restrict__ sbi,
             int n, float* __restrict__ out) {
    extern __shared__ char dynsm[];
    __shared__ float sh[SH_FLOATS];
    __shared__ unsigned long long mbars[4];   // [0,1]=phase A, [2,3]=phase C
    __shared__ int sh_last;
    float* s_sum = sh;                 // stride 17 (phase A)
    float* s_mu  = sh;                 // dense stride 16 (phase C)
    float* s_cnt = sh + NSEG * 17;     // also s_iv in phase C
    float* s_red = sh + NSEG * 17 + NSEG;

    const int t   = threadIdx.x;
    const int bd  = TPB;
    const int wid = t >> 5, lid = t & 31;
    const int pg  = t >> 2;            // point-group (4 lanes per point)
    const int c4  = t & 3;             // chunk within point
    const char* gdata = (const char*)out4;

    unsigned mb[4];
    {
        unsigned base = (unsigned)__cvta_generic_to_shared(mbars);
#pragma unroll
        for (int i = 0; i < 4; i++) mb[i] = base + i * 8;
    }
    if (t == 0) {
#pragma unroll
        for (int i = 0; i < 4; i++) mbar_init(mb[i], 1);
    }
    asm volatile("fence.proxy.async.shared::cta;" ::: "memory");
    __syncthreads();

    // ---- chunk for this block ----
    int per = (n + GRID - 1) / GRID;
    per = ((per + bd - 1) / bd) * bd;
    int start = blockIdx.x * per;
    int end   = start + per; if (end > n) end = n;
    const int cnt_pts = (end > start) ? (end - start) : 0;
    const int nt  = cnt_pts / TILE;
    const int rem = cnt_pts - nt * TILE;

    // ---- phase A prologue FIRST: fetch overlaps smem init ----
    if (t == 0) {
        if (nt > 0) issue_tile(dynsm,           mb[0], gdata, lab, sbi, start);
        if (nt > 1) issue_tile(dynsm + STAGE_B, mb[1], gdata, lab, sbi, start + TILE);
    }

    // ================= PHASE A : segment sums of normalized x =============
    for (int i = t; i < NSEG * 17; i += bd) s_sum[i] = 0.0f;
    for (int i = t; i < NSEG; i += bd)      s_cnt[i] = 0.0f;
    __syncthreads();

    {
        float4 acc = make_float4(0.f, 0.f, 0.f, 0.f);
        float  cw  = 0.0f;
        int    cur = -1;

        auto flush = [&]() {
            if (cur >= 0) {
                atomicAdd(&s_sum[cur * 17 + c4 * 4 + 0], acc.x);
                atomicAdd(&s_sum[cur * 17 + c4 * 4 + 1], acc.y);
                atomicAdd(&s_sum[cur * 17 + c4 * 4 + 2], acc.z);
                atomicAdd(&s_sum[cur * 17 + c4 * 4 + 3], acc.w);
                if (c4 == 0) atomicAdd(&s_cnt[cur], cw);
            }
        };

        for (int k = 0; k < nt; k++) {
            mbar_wait(mb[k & 1], (k >> 1) & 1);
            char* stg = dynsm + (k & 1) * STAGE_B;
#pragma unroll
            for (int j = 0; j < TILE / 128; j++) {
                int q = pg + j * 128;                   // label-invariant stride
                float4 v = *(const float4*)(stg + q * 64 + c4 * 16);
                int l = ((const int*)(stg + LAB_OFF))[q];
                int s = ((const int*)(stg + SBI_OFF))[q];
                float pd = v.x*v.x + v.y*v.y + v.z*v.z + v.w*v.w;
                pd += __shfl_xor_sync(0xFFFFFFFFu, pd, 1);
                pd += __shfl_xor_sync(0xFFFFFFFFu, pd, 2);
                float inv = rsqrtf(pd);
                int seg = s * MLAB + l;
                if (seg != cur) {
                    flush();
                    cur = seg; cw = 0.0f;
                    acc = make_float4(0.f, 0.f, 0.f, 0.f);
                }
                acc.x += v.x * inv;  acc.y += v.y * inv;
                acc.z += v.z * inv;  acc.w += v.w * inv;
                cw += 1.0f;
            }
            __syncthreads();                  // all readers done with this stage
            if (t == 0 && k + 2 < nt)
                issue_tile(stg, mb[k & 1], gdata, lab, sbi, start + (k + 2) * TILE);
        }

        // ---- EARLY phase C prologue: fetch tail tiles during barrier/B ----
        if (t == 0) {
            if (nt > 0) issue_tile(dynsm,           mb[2], gdata, lab, sbi,
                                   start + (nt - 1) * TILE);
            if (nt > 1) issue_tile(dynsm + STAGE_B, mb[3], gdata, lab, sbi,
                                   start + (nt - 2) * TILE);
        }

        // ragged tail: direct scalar path
        if (t < rem) {
            int p = start + nt * TILE + t;
            const float4* r = out4 + (size_t)p * 4;
            float4 a = r[0], b = r[1], c = r[2], e = r[3];
            float inv = rsqrtf(dot16(a, b, c, e));
            int seg = sbi[p] * MLAB + lab[p];
            float xs[16] = {a.x,a.y,a.z,a.w, b.x,b.y,b.z,b.w,
                            c.x,c.y,c.z,c.w, e.x,e.y,e.z,e.w};
#pragma unroll
            for (int d = 0; d < 16; d++) atomicAdd(&s_sum[seg * 17 + d], xs[d] * inv);
            atomicAdd(&s_cnt[seg], 1.0f);
        }
        flush();
    }
    __syncthreads();

    // block flush -> global atomics
    for (int s = t; s < NSEG; s += bd) {
        float c0 = s_cnt[s];
        if (c0 != 0.0f) {
            atomicAdd(&g_cnts[s], c0);
#pragma unroll
            for (int d = 0; d < 16; d++)
                atomicAdd(&g_sums[s * 16 + d], s_sum[s * 17 + d]);
        }
    }

    // ================= GRID BARRIER (C-tile fetch in flight) =============
    __threadfence();
    __syncthreads();
    if (t == 0) {
        atomicAdd(&g_bar1, 1u);
        while (atomicAdd(&g_bar1, 0u) < (unsigned)GRID) { __nanosleep(64); }
    }
    __syncthreads();
    __threadfence();

    // ================= PHASE B : centroids (replicated per block) =========
    if (t < NSEG) {
        float c  = __ldcg(&g_cnts[t]);
        float ic = 1.0f / c;
        const float4* gs = (const float4*)&g_sums[t * 16];
        float4 m0 = __ldcg(gs + 0), m1 = __ldcg(gs + 1),
               m2 = __ldcg(gs + 2), m3 = __ldcg(gs + 3);
        float4* sm = (float4*)&s_mu[t * 16];
        m0.x *= ic; m0.y *= ic; m0.z *= ic; m0.w *= ic;
        m1.x *= ic; m1.y *= ic; m1.z *= ic; m1.w *= ic;
        m2.x *= ic; m2.y *= ic; m2.z *= ic; m2.w *= ic;
        m3.x *= ic; m3.y *= ic; m3.z *= ic; m3.w *= ic;
        sm[0] = m0; sm[1] = m1; sm[2] = m2; sm[3] = m3;
        s_cnt[t] = 1.0f / ((float)MLAB * c);    // s_iv
    }
    __syncthreads();

    // push term: block 0 only
    if (blockIdx.x == 0) {
        float h = 0.0f;
        if (t < NSEG) {
            int b = t >> 5, ii = t & 31;
            const float* mi = &s_mu[t * 16];
            for (int j = 0; j < MLAB; j++) {
                if (j == ii) continue;
                const float* mj = &s_mu[(b * 32 + j) * 16];
                float pd = 0.0f;
#pragma unroll
                for (int d = 0; d < 16; d++) pd += fabsf(mi[d] - mj[d]);
                float tt = TWO_DELTA_D - pd;
                if (tt > 0.0f) h += tt * tt;
            }
        }
        for (int off = 16; off > 0; off >>= 1)
            h += __shfl_down_sync(0xFFFFFFFFu, h, off);
        if (lid == 0) s_red[wid] = h;
        __syncthreads();
        if (t == 0) {
            float v = 0.0f;
            for (int w = 0; w < TPB / 32; w++) v += s_red[w];
            g_push = v / ((float)MLAB * (float)(MLAB - 1));
        }
    }

    // ================= PHASE C : pull term (reverse tiles, prefetched) ====
    float local = 0.0f;
    {
        // ragged tail (chunk end = most recently streamed): direct loads
        if (t < rem) {
            int p = start + nt * TILE + t;
            const float4* r = out4 + (size_t)p * 4;
            float4 a = r[0], b = r[1], c = r[2], e = r[3];
            float inv = rsqrtf(dot16(a, b, c, e));
            int seg = sbi[p] * MLAB + lab[p];
            const float* mu = &s_mu[seg * 16];
            float xs[16] = {a.x,a.y,a.z,a.w, b.x,b.y,b.z,b.w,
                            c.x,c.y,c.z,c.w, e.x,e.y,e.z,e.w};
            float dist = 0.0f;
#pragma unroll
            for (int d = 0; d < 16; d++) dist += fabsf(fmaf(xs[d], inv, -mu[d]));
            float tt = dist - DELTA_V;
            if (tt > 0.0f) local += tt * tt * s_cnt[seg];
        }

        for (int j = 0; j < nt; j++) {        // tile index = nt-1-j (reverse)
            mbar_wait(mb[2 + (j & 1)], (j >> 1) & 1);
            char* stg = dynsm + (j & 1) * STAGE_B;
#pragma unroll
            for (int jj = 0; jj < TILE / 128; jj++) {
                int q = pg + jj * 128;
                float4 v = *(const float4*)(stg + q * 64 + c4 * 16);
                int l = ((const int*)(stg + LAB_OFF))[q];
                int s = ((const int*)(stg + SBI_OFF))[q];
                float pd = v.x*v.x + v.y*v.y + v.z*v.z + v.w*v.w;
                pd += __shfl_xor_sync(0xFFFFFFFFu, pd, 1);
                pd += __shfl_xor_sync(0xFFFFFFFFu, pd, 2);
                float inv = rsqrtf(pd);
                int seg = s * MLAB + l;
                float4 m = *(const float4*)&s_mu[seg * 16 + c4 * 4];
                float pdist = fabsf(fmaf(v.x, inv, -m.x)) + fabsf(fmaf(v.y, inv, -m.y))
                            + fabsf(fmaf(v.z, inv, -m.z)) + fabsf(fmaf(v.w, inv, -m.w));
                pdist += __shfl_xor_sync(0xFFFFFFFFu, pdist, 1);
                pdist += __shfl_xor_sync(0xFFFFFFFFu, pdist, 2);
                if (c4 == 0) {
                    float tt = pdist - DELTA_V;
                    if (tt > 0.0f) local += tt * tt * s_cnt[seg];   // s_iv
                }
            }
            __syncthreads();
            if (t == 0 && j + 2 < nt)
                issue_tile(stg, mb[2 + (j & 1)], gdata, lab, sbi,
                           start + (nt - 3 - j) * TILE);
        }
    }

    // block reduction of pull
    for (int off = 16; off > 0; off >>= 1)
        local += __shfl_down_sync(0xFFFFFFFFu, local, off);
    if (lid == 0) s_red[wid] = local;
    __syncthreads();
    if (t == 0) {
        float v = 0.0f;
        for (int w = 0; w < TPB / 32; w++) v += s_red[w];
        atomicAdd(&g_pull, v);
    }

    // ================= EXIT: last block finalizes + resets ================
    if (t == 0) {
        __threadfence();
        unsigned old = atomicAdd(&g_bar2, 1u);
        sh_last = (old == (unsigned)GRID - 1u) ? 1 : 0;
    }
    __syncthreads();
    if (sh_last) {
        for (int i = t; i < NSEG * 16; i += bd) g_sums[i] = 0.0f;
        for (int i = t; i < NSEG; i += bd)      g_cnts[i] = 0.0f;
        if (t == 0) {
            float pull = atomicAdd(&g_pull, 0.0f);
            float push = g_push;
            out[0] = (pull + push) * (1.0f / (float)BSUB);
            g_pull = 0.0f;
            g_push = 0.0f;
            g_bar1 = 0u;
            g_bar2 = 0u;
        }
    }
}

extern "C" void kernel_launch(void* const* d_in, const int* in_sizes, int n_in,
                              void* d_out, int out_size) {
    const float4* out4 = (const float4*)d_in[0];
    const int*    lab  = (const int*)d_in[1];
    const int*    sbi  = (const int*)d_in[2];
    float* out = (float*)d_out;
    int n = in_sizes[1];   // N points

    static bool attr_ok = false;
    if (!attr_ok) {
        cudaError_t e = cudaFuncSetAttribute(
            k_fused, cudaFuncAttributeMaxDynamicSharedMemorySize, DYN_B);
        attr_ok = (e == cudaSuccess);
    }
    k_fused<<<GRID, TPB, DYN_B>>>(out4, lab, sbi, n, out);
}